// round 13
// baseline (speedup 1.0000x reference)
#include <cuda_runtime.h>
#include <cuda_fp16.h>
#include <cstdint>

#define HW   512
#define NTHR 256
#define TPW  34
#define TPH  6
#define XS_CH (TPH * TPW)        // 204
#define TILES_PER_CTA 8
#define N_TILES 8192             // 4 batches * 16 * 128 tiles of 32x4

// smem layout (float/u32 offsets)
// Region at H_OFF is time-shared: startup {w0h, b0s} -> per tile: ys2, then H.
#define XS_OFF 0                 // [16][204] = 3264
#define H_STR  136
#define H_OFF  3264              // H: [128][136] fp32 = 17408
#define REGION 17408
#define W0H_OFF H_OFF            // staging: [128][24] u32 half2 = 3072 (startup only)
#define B0_OFF  (H_OFF + 3072)   // staging: 128 (startup only)
#define YS2_STR 132
#define YS2_OFF H_OFF            // ys2: [24][132] u32 half2 = 3168 (per tile, pre-H)
#define W1_STR 132
#define W1_OFF (H_OFF + REGION)         // 20672 ; [16][132] = 2112
#define MS_OFF (W1_OFF + 2112)          // 22784
#define SM_FLOATS (MS_OFF + 128)        // 22912 floats = 91648 B

__device__ __forceinline__ float tf32f(float f) {
    uint32_t u;
    asm("cvt.rna.tf32.f32 %0, %1;" : "=r"(u) : "f"(f));
    return __uint_as_float(u);
}
__device__ __forceinline__ uint32_t packh2(float lo, float hi) {
    __half2 h = __floats2half2_rn(lo, hi);
    return *(uint32_t*)&h;
}

// tf32: D += A(16x8) * B(8x8)
__device__ __forceinline__ void mma8(float* d, const float* a, float b0, float b1) {
    asm("mma.sync.aligned.m16n8k8.row.col.f32.tf32.tf32.f32 "
        "{%0,%1,%2,%3}, {%4,%5,%6,%7}, {%8,%9}, {%0,%1,%2,%3};"
        : "+f"(d[0]), "+f"(d[1]), "+f"(d[2]), "+f"(d[3])
        : "r"(__float_as_uint(a[0])), "r"(__float_as_uint(a[1])),
          "r"(__float_as_uint(a[2])), "r"(__float_as_uint(a[3])),
          "r"(__float_as_uint(b0)), "r"(__float_as_uint(b1)));
}
// fp16: D += A(16x8) * B(8x8); A = 2 regs (half2), B = 1 reg (half2)
__device__ __forceinline__ void mma8h(float* d, uint32_t a0, uint32_t a1, uint32_t b) {
    asm("mma.sync.aligned.m16n8k8.row.col.f32.f16.f16.f32 "
        "{%0,%1,%2,%3}, {%4,%5}, {%6}, {%0,%1,%2,%3};"
        : "+f"(d[0]), "+f"(d[1]), "+f"(d[2]), "+f"(d[3])
        : "r"(a0), "r"(a1), "r"(b));
}

__global__ __launch_bounds__(NTHR, 2)
void ca_mma_kernel(const float* __restrict__ x,
                   const float* __restrict__ w0,
                   const float* __restrict__ b0,
                   const float* __restrict__ w1,
                   const float* __restrict__ rand_u,
                   float* __restrict__ out)
{
    extern __shared__ float sm[];
    float*    xs   = sm + XS_OFF;
    float*    Hs   = sm + H_OFF;
    uint32_t* w0h  = (uint32_t*)(sm + W0H_OFF);   // startup only (aliased)
    float*    b0s  = sm + B0_OFF;                 // startup only (aliased)
    uint32_t* ys2  = (uint32_t*)(sm + YS2_OFF);   // per tile, aliased with Hs
    float*    w1s  = sm + W1_OFF;
    float*    ms   = sm + MS_OFF;

    const int tid  = threadIdx.x;
    const int lane = tid & 31;
    const int wid  = tid >> 5;
    const int g    = lane >> 2;   // groupID
    const int t    = lane & 3;    // thread-in-group

    // ---- stage weights: w0 as half2-packed [128][24], w1 tf32 [16][132] ----
    for (int i = tid; i < 128 * 24; i += NTHR) {
        int r = i / 24, c = i - r * 24;
        w0h[r * 24 + c] = packh2(w0[r * 48 + 2 * c], w0[r * 48 + 2 * c + 1]);
    }
    for (int i = tid; i < 16 * 128; i += NTHR) {
        int r = i >> 7, c = i & 127;
        w1s[r * W1_STR + c] = tf32f(w1[i]);
    }
    if (tid < 128) b0s[tid] = b0[tid];
    __syncthreads();

    // ---- persistent W0 A-fragments (fp16): warp owns hid rows [16*wid, +16) ----
    uint32_t a1f2[6][2];
    {
        const int r0 = 16 * wid + g;
        #pragma unroll
        for (int s = 0; s < 6; s++) {
            a1f2[s][0] = w0h[r0 * 24 + 4 * s + t];
            a1f2[s][1] = w0h[(r0 + 8) * 24 + 4 * s + t];
        }
    }
    const float bias0 = b0s[16 * wid + g];
    const float bias1 = b0s[16 * wid + g + 8];

    const int px_  = tid & 127;          // feature pixel for this thread
    const int fsel = tid >> 7;           // which 8 channels
    const int fpy  = px_ >> 5, fpx = px_ & 31;

    // halo loader role: threads 0..203 each load 16 channels of one (hy,hx)
    const int hpos = tid;
    const int hhy  = hpos / TPW;
    const int hhx  = hpos - hhy * TPW;

    const int tile0 = blockIdx.x * TILES_PER_CTA;
    for (int it = 0; it < TILES_PER_CTA; ++it) {
        const int tile = tile0 + it;
        const int b    = tile >> 11;
        const int rem  = tile & 2047;
        const int gh0  = (rem >> 4) * 4;
        const int gw0  = (rem & 15) * 32;

        __syncthreads();   // prev tile's readers of xs/ms/Hs done

        // ---- halo load (zero pad): 204 workers x 16 channels ----
        if (hpos < XS_CH) {
            const int gh = gh0 + hhy - 1, gw = gw0 + hhx - 1;
            if (gh >= 0 && gh < HW && gw >= 0 && gw < HW) {
                const float* gp = x + ((size_t)b << 22) + ((size_t)(gh << 9) + gw);
                #pragma unroll
                for (int c = 0; c < 16; c++)
                    xs[c * XS_CH + hpos] = gp[(size_t)c << 18];
            } else {
                #pragma unroll
                for (int c = 0; c < 16; c++)
                    xs[c * XS_CH + hpos] = 0.f;
            }
        }
        if (tid < 128) {
            int gh = gh0 + (tid >> 5), gw = gw0 + (tid & 31);
            ms[tid] = rand_u[((size_t)b << 18) + (gh << 9) + gw] > 0.5f ? 1.f : 0.f;
        }
        __syncthreads();

        // ---- features (fp16-packed over channel pairs): rows k/2 of ys2 ----
        {
            const int cb = fsel * 8;
            float xv[8], gxv[8], gyv[8];
            #pragma unroll
            for (int c = 0; c < 8; c++) {
                const float* p = xs + (cb + c) * XS_CH + fpy * TPW + fpx;
                float a00 = p[0],       a01 = p[1],           a02 = p[2];
                float a10 = p[TPW],     a11 = p[TPW + 1],     a12 = p[TPW + 2];
                float a20 = p[2*TPW],   a21 = p[2*TPW + 1],   a22 = p[2*TPW + 2];
                xv[c]  = a11;
                gxv[c] = (a02 - a00) + 2.f * (a12 - a10) + (a22 - a20);
                gyv[c] = (a20 - a00) + 2.f * (a21 - a01) + (a22 - a02);
            }
            const int rb = cb >> 1;   // 0 or 4
            #pragma unroll
            for (int i = 0; i < 4; i++) {
                ys2[(rb + i) * YS2_STR + px_]      = packh2(xv[2*i],  xv[2*i+1]);
                ys2[(8 + rb + i) * YS2_STR + px_]  = packh2(gxv[2*i], gxv[2*i+1]);
                ys2[(16 + rb + i) * YS2_STR + px_] = packh2(gyv[2*i], gyv[2*i+1]);
            }
        }
        __syncthreads();

        // ---- GEMM1 (fp16) both 64-px halves: warp = 16 hid rows x 128 px ----
        float acc[2][8][4];
        #pragma unroll
        for (int sub = 0; sub < 2; sub++)
            #pragma unroll
            for (int j = 0; j < 8; j++) {
                acc[sub][j][0] = bias0; acc[sub][j][1] = bias0;
                acc[sub][j][2] = bias1; acc[sub][j][3] = bias1;
            }
        #pragma unroll
        for (int s = 0; s < 6; s++) {
            const uint32_t a0 = a1f2[s][0], a1 = a1f2[s][1];
            #pragma unroll
            for (int sub = 0; sub < 2; sub++) {
                const uint32_t* yb = ys2 + (4 * s + t) * YS2_STR + 64 * sub + g;
                #pragma unroll
                for (int j = 0; j < 8; j++)
                    mma8h(acc[sub][j], a0, a1, yb[8 * j]);
            }
        }
        __syncthreads();   // all ys2 reads done; region becomes H

        // ---- relu -> tf32 -> H[hid][128] fp32 (R9 addresses, float2-paired) ----
        {
            const int hr = 16 * wid + g;
            #pragma unroll
            for (int sub = 0; sub < 2; sub++) {
                #pragma unroll
                for (int j = 0; j < 8; j++) {
                    int cc = 64 * sub + 8 * j + 2 * t;
                    float2 v0 = { tf32f(fmaxf(acc[sub][j][0], 0.f)),
                                  tf32f(fmaxf(acc[sub][j][1], 0.f)) };
                    float2 v1 = { tf32f(fmaxf(acc[sub][j][2], 0.f)),
                                  tf32f(fmaxf(acc[sub][j][3], 0.f)) };
                    *(float2*)(Hs + hr * H_STR + cc)       = v0;
                    *(float2*)(Hs + (hr + 8) * H_STR + cc) = v1;
                }
            }
        }
        __syncthreads();   // H ready

        // ---- GEMM2 (tf32, unchanged): both halves in one k-loop ----
        float acc2[2][4] = {{0.f,0.f,0.f,0.f},{0.f,0.f,0.f,0.f}};
        #pragma unroll
        for (int s = 0; s < 16; s++) {
            float aa[4];
            aa[0] = w1s[g * W1_STR + 8 * s + t];
            aa[1] = w1s[(g + 8) * W1_STR + 8 * s + t];
            aa[2] = w1s[g * W1_STR + 8 * s + t + 4];
            aa[3] = w1s[(g + 8) * W1_STR + 8 * s + t + 4];
            const float* hb0 = Hs + (8 * s + t) * H_STR + 8 * wid + g;
            const float* hb1 = Hs + (8 * s + t + 4) * H_STR + 8 * wid + g;
            mma8(acc2[0], aa, hb0[0],  hb1[0]);
            mma8(acc2[1], aa, hb0[64], hb1[64]);
        }

        // ---- epilogue per half (R4 EXACT, pxb = 64*sub) ----
        #pragma unroll
        for (int sub = 0; sub < 2; sub++) {
            const int cl = 8 * wid + 2 * t;
            const int p  = 64 * sub + cl;
            const int py = p >> 5, pxw = p & 31;
            const float m0 = ms[p], m1 = ms[p + 1];
            const int ch = g, ch2 = g + 8;
            const float* xc0 = xs + ch  * XS_CH + (py + 1) * TPW + pxw + 1;
            const float* xc1 = xs + ch2 * XS_CH + (py + 1) * TPW + pxw + 1;
            size_t o0 = ((size_t)(b * 16 + ch)  << 18) + ((size_t)(gh0 + py) << 9) + gw0 + pxw;
            size_t o1 = ((size_t)(b * 16 + ch2) << 18) + ((size_t)(gh0 + py) << 9) + gw0 + pxw;
            float2 v0 = { xc0[0] + acc2[sub][0] * m0, xc0[1] + acc2[sub][1] * m1 };
            float2 v1 = { xc1[0] + acc2[sub][2] * m0, xc1[1] + acc2[sub][3] * m1 };
            *(float2*)(out + o0) = v0;
            *(float2*)(out + o1) = v1;
        }
    }
}

extern "C" void kernel_launch(void* const* d_in, const int* in_sizes, int n_in,
                              void* d_out, int out_size)
{
    const float* x      = (const float*)d_in[0];
    const float* w0     = (const float*)d_in[1];
    const float* b0     = (const float*)d_in[2];
    const float* w1     = (const float*)d_in[3];
    const float* rand_u = (const float*)d_in[4];
    float* out = (float*)d_out;

    const int smem_bytes = SM_FLOATS * sizeof(float);   // 91648 B
    cudaFuncSetAttribute(ca_mma_kernel, cudaFuncAttributeMaxDynamicSharedMemorySize,
                         smem_bytes);
    dim3 grid(N_TILES / TILES_PER_CTA);  // 1024 CTAs
    ca_mma_kernel<<<grid, NTHR, smem_bytes>>>(x, w0, b0, w1, rand_u, out);
}

// round 14
// speedup vs baseline: 1.1382x; 1.1382x over previous
#include <cuda_runtime.h>
#include <cuda_fp16.h>
#include <cstdint>

#define HW   512
#define NTHR 256
#define TPW  34
#define TPH  6
#define XS_CH (TPH * TPW)        // 204
#define TILES_PER_CTA 8
#define N_TILES 8192             // 4 batches * 16 * 128 tiles of 32x4

// smem layout (float/u32 offsets)
// Region at H_OFF is time-shared: startup {w0h, b0s} -> per tile: ys2, then H.
#define XS_OFF 0                 // [16][204] = 3264
#define H_STR  136
#define H_OFF  3264              // H: [128][136] fp32 = 17408
#define REGION 17408
#define W0H_OFF H_OFF            // staging: [128][24] u32 half2 = 3072 (startup only)
#define B0_OFF  (H_OFF + 3072)   // staging: 128 (startup only)
#define YS2_STR 136
#define YS2_OFF H_OFF            // ys2: [24][136] u32 half2 = 3264 (per tile, pre-H)
#define W1_STR 132
#define W1_OFF (H_OFF + REGION)         // 20672 ; [16][132] = 2112
#define MS_OFF (W1_OFF + 2112)          // 22784
#define SM_FLOATS (MS_OFF + 128)        // 22912 floats = 91648 B

__device__ __forceinline__ float tf32f(float f) {
    uint32_t u;
    asm("cvt.rna.tf32.f32 %0, %1;" : "=r"(u) : "f"(f));
    return __uint_as_float(u);
}
__device__ __forceinline__ uint32_t packh2(float lo, float hi) {
    __half2 h = __floats2half2_rn(lo, hi);
    return *(uint32_t*)&h;
}

// tf32: D += A(16x8) * B(8x8)
__device__ __forceinline__ void mma8(float* d, const float* a, float b0, float b1) {
    asm("mma.sync.aligned.m16n8k8.row.col.f32.tf32.tf32.f32 "
        "{%0,%1,%2,%3}, {%4,%5,%6,%7}, {%8,%9}, {%0,%1,%2,%3};"
        : "+f"(d[0]), "+f"(d[1]), "+f"(d[2]), "+f"(d[3])
        : "r"(__float_as_uint(a[0])), "r"(__float_as_uint(a[1])),
          "r"(__float_as_uint(a[2])), "r"(__float_as_uint(a[3])),
          "r"(__float_as_uint(b0)), "r"(__float_as_uint(b1)));
}
// fp16 native shape: D(16x8) += A(16x16) * B(16x8); A = 4 regs, B = 2 regs
__device__ __forceinline__ void mma16h(float* d, uint32_t a0, uint32_t a1,
                                       uint32_t a2, uint32_t a3,
                                       uint32_t b0, uint32_t b1) {
    asm("mma.sync.aligned.m16n8k16.row.col.f32.f16.f16.f32 "
        "{%0,%1,%2,%3}, {%4,%5,%6,%7}, {%8,%9}, {%0,%1,%2,%3};"
        : "+f"(d[0]), "+f"(d[1]), "+f"(d[2]), "+f"(d[3])
        : "r"(a0), "r"(a1), "r"(a2), "r"(a3), "r"(b0), "r"(b1));
}

__global__ __launch_bounds__(NTHR, 2)
void ca_mma_kernel(const float* __restrict__ x,
                   const float* __restrict__ w0,
                   const float* __restrict__ b0,
                   const float* __restrict__ w1,
                   const float* __restrict__ rand_u,
                   float* __restrict__ out)
{
    extern __shared__ float sm[];
    float*    xs   = sm + XS_OFF;
    float*    Hs   = sm + H_OFF;
    uint32_t* w0h  = (uint32_t*)(sm + W0H_OFF);   // startup only (aliased)
    float*    b0s  = sm + B0_OFF;                 // startup only (aliased)
    uint32_t* ys2  = (uint32_t*)(sm + YS2_OFF);   // per tile, aliased with Hs
    float*    w1s  = sm + W1_OFF;
    float*    ms   = sm + MS_OFF;

    const int tid  = threadIdx.x;
    const int lane = tid & 31;
    const int wid  = tid >> 5;
    const int g    = lane >> 2;   // groupID
    const int t    = lane & 3;    // thread-in-group

    // ---- stage weights: w0 as half2-packed [128][24], w1 tf32 [16][132] ----
    for (int i = tid; i < 128 * 24; i += NTHR) {
        int r = i / 24, c = i - r * 24;
        w0h[r * 24 + c] = packh2(w0[r * 48 + 2 * c], w0[r * 48 + 2 * c + 1]);
    }
    for (int i = tid; i < 16 * 128; i += NTHR) {
        int r = i >> 7, c = i & 127;
        w1s[r * W1_STR + c] = tf32f(w1[i]);
    }
    if (tid < 128) b0s[tid] = b0[tid];
    __syncthreads();

    // ---- persistent W0 A-fragments (fp16 k16): warp owns hid rows [16*wid,+16) ----
    // k-step s covers k in [16s,16s+16): a0=(g,2t..), a1=(g+8,2t..), a2=(g,2t+8..), a3=(g+8,2t+8..)
    uint32_t a1f2[3][4];
    {
        const int r0 = 16 * wid + g;
        #pragma unroll
        for (int s = 0; s < 3; s++) {
            a1f2[s][0] = w0h[r0 * 24 + 8 * s + t];
            a1f2[s][1] = w0h[(r0 + 8) * 24 + 8 * s + t];
            a1f2[s][2] = w0h[r0 * 24 + 8 * s + t + 4];
            a1f2[s][3] = w0h[(r0 + 8) * 24 + 8 * s + t + 4];
        }
    }
    const float bias0 = b0s[16 * wid + g];
    const float bias1 = b0s[16 * wid + g + 8];

    const int px_  = tid & 127;          // feature pixel for this thread
    const int fsel = tid >> 7;           // which 8 channels
    const int fpy  = px_ >> 5, fpx = px_ & 31;

    // halo loader role: threads 0..203 each load 16 channels of one (hy,hx)
    const int hpos = tid;
    const int hhy  = hpos / TPW;
    const int hhx  = hpos - hhy * TPW;

    const int tile0 = blockIdx.x * TILES_PER_CTA;
    for (int it = 0; it < TILES_PER_CTA; ++it) {
        const int tile = tile0 + it;
        const int b    = tile >> 11;
        const int rem  = tile & 2047;
        const int gh0  = (rem >> 4) * 4;
        const int gw0  = (rem & 15) * 32;

        __syncthreads();   // prev tile's readers of xs/ms/Hs done

        // ---- halo load (zero pad): 204 workers x 16 channels ----
        if (hpos < XS_CH) {
            const int gh = gh0 + hhy - 1, gw = gw0 + hhx - 1;
            if (gh >= 0 && gh < HW && gw >= 0 && gw < HW) {
                const float* gp = x + ((size_t)b << 22) + ((size_t)(gh << 9) + gw);
                #pragma unroll
                for (int c = 0; c < 16; c++)
                    xs[c * XS_CH + hpos] = gp[(size_t)c << 18];
            } else {
                #pragma unroll
                for (int c = 0; c < 16; c++)
                    xs[c * XS_CH + hpos] = 0.f;
            }
        }
        if (tid < 128) {
            int gh = gh0 + (tid >> 5), gw = gw0 + (tid & 31);
            ms[tid] = rand_u[((size_t)b << 18) + (gh << 9) + gw] > 0.5f ? 1.f : 0.f;
        }
        __syncthreads();

        // ---- features (fp16-packed over channel pairs): rows k/2 of ys2 ----
        {
            const int cb = fsel * 8;
            float xv[8], gxv[8], gyv[8];
            #pragma unroll
            for (int c = 0; c < 8; c++) {
                const float* p = xs + (cb + c) * XS_CH + fpy * TPW + fpx;
                float a00 = p[0],       a01 = p[1],           a02 = p[2];
                float a10 = p[TPW],     a11 = p[TPW + 1],     a12 = p[TPW + 2];
                float a20 = p[2*TPW],   a21 = p[2*TPW + 1],   a22 = p[2*TPW + 2];
                xv[c]  = a11;
                gxv[c] = (a02 - a00) + 2.f * (a12 - a10) + (a22 - a20);
                gyv[c] = (a20 - a00) + 2.f * (a21 - a01) + (a22 - a02);
            }
            const int rb = cb >> 1;   // 0 or 4
            #pragma unroll
            for (int i = 0; i < 4; i++) {
                ys2[(rb + i) * YS2_STR + px_]      = packh2(xv[2*i],  xv[2*i+1]);
                ys2[(8 + rb + i) * YS2_STR + px_]  = packh2(gxv[2*i], gxv[2*i+1]);
                ys2[(16 + rb + i) * YS2_STR + px_] = packh2(gyv[2*i], gyv[2*i+1]);
            }
        }
        __syncthreads();

        // ---- GEMM1 (fp16 k16): 3 k-steps, both 64-px halves ----
        // B rows (in ys2 half2 rows): 8s+t and 8s+t+4 — same pattern as tf32 R9.
        float acc[2][8][4];
        #pragma unroll
        for (int sub = 0; sub < 2; sub++)
            #pragma unroll
            for (int j = 0; j < 8; j++) {
                acc[sub][j][0] = bias0; acc[sub][j][1] = bias0;
                acc[sub][j][2] = bias1; acc[sub][j][3] = bias1;
            }
        #pragma unroll
        for (int s = 0; s < 3; s++) {
            const uint32_t a0 = a1f2[s][0], a1 = a1f2[s][1];
            const uint32_t a2 = a1f2[s][2], a3 = a1f2[s][3];
            #pragma unroll
            for (int sub = 0; sub < 2; sub++) {
                const uint32_t* yb0 = ys2 + (8 * s + t) * YS2_STR + 64 * sub + g;
                const uint32_t* yb1 = ys2 + (8 * s + t + 4) * YS2_STR + 64 * sub + g;
                #pragma unroll
                for (int j = 0; j < 8; j++)
                    mma16h(acc[sub][j], a0, a1, a2, a3, yb0[8 * j], yb1[8 * j]);
            }
        }
        __syncthreads();   // all ys2 reads done; region becomes H

        // ---- relu -> tf32 -> H[hid][128] fp32 (R9 addresses, float2-paired) ----
        {
            const int hr = 16 * wid + g;
            #pragma unroll
            for (int sub = 0; sub < 2; sub++) {
                #pragma unroll
                for (int j = 0; j < 8; j++) {
                    int cc = 64 * sub + 8 * j + 2 * t;
                    float2 v0 = { tf32f(fmaxf(acc[sub][j][0], 0.f)),
                                  tf32f(fmaxf(acc[sub][j][1], 0.f)) };
                    float2 v1 = { tf32f(fmaxf(acc[sub][j][2], 0.f)),
                                  tf32f(fmaxf(acc[sub][j][3], 0.f)) };
                    *(float2*)(Hs + hr * H_STR + cc)       = v0;
                    *(float2*)(Hs + (hr + 8) * H_STR + cc) = v1;
                }
            }
        }
        __syncthreads();   // H ready

        // ---- GEMM2 (tf32, unchanged): both halves in one k-loop ----
        float acc2[2][4] = {{0.f,0.f,0.f,0.f},{0.f,0.f,0.f,0.f}};
        #pragma unroll
        for (int s = 0; s < 16; s++) {
            float aa[4];
            aa[0] = w1s[g * W1_STR + 8 * s + t];
            aa[1] = w1s[(g + 8) * W1_STR + 8 * s + t];
            aa[2] = w1s[g * W1_STR + 8 * s + t + 4];
            aa[3] = w1s[(g + 8) * W1_STR + 8 * s + t + 4];
            const float* hb0 = Hs + (8 * s + t) * H_STR + 8 * wid + g;
            const float* hb1 = Hs + (8 * s + t + 4) * H_STR + 8 * wid + g;
            mma8(acc2[0], aa, hb0[0],  hb1[0]);
            mma8(acc2[1], aa, hb0[64], hb1[64]);
        }

        // ---- epilogue per half (R4 EXACT, pxb = 64*sub) ----
        #pragma unroll
        for (int sub = 0; sub < 2; sub++) {
            const int cl = 8 * wid + 2 * t;
            const int p  = 64 * sub + cl;
            const int py = p >> 5, pxw = p & 31;
            const float m0 = ms[p], m1 = ms[p + 1];
            const int ch = g, ch2 = g + 8;
            const float* xc0 = xs + ch  * XS_CH + (py + 1) * TPW + pxw + 1;
            const float* xc1 = xs + ch2 * XS_CH + (py + 1) * TPW + pxw + 1;
            size_t o0 = ((size_t)(b * 16 + ch)  << 18) + ((size_t)(gh0 + py) << 9) + gw0 + pxw;
            size_t o1 = ((size_t)(b * 16 + ch2) << 18) + ((size_t)(gh0 + py) << 9) + gw0 + pxw;
            float2 v0 = { xc0[0] + acc2[sub][0] * m0, xc0[1] + acc2[sub][1] * m1 };
            float2 v1 = { xc1[0] + acc2[sub][2] * m0, xc1[1] + acc2[sub][3] * m1 };
            *(float2*)(out + o0) = v0;
            *(float2*)(out + o1) = v1;
        }
    }
}

extern "C" void kernel_launch(void* const* d_in, const int* in_sizes, int n_in,
                              void* d_out, int out_size)
{
    const float* x      = (const float*)d_in[0];
    const float* w0     = (const float*)d_in[1];
    const float* b0     = (const float*)d_in[2];
    const float* w1     = (const float*)d_in[3];
    const float* rand_u = (const float*)d_in[4];
    float* out = (float*)d_out;

    const int smem_bytes = SM_FLOATS * sizeof(float);   // 91648 B
    cudaFuncSetAttribute(ca_mma_kernel, cudaFuncAttributeMaxDynamicSharedMemorySize,
                         smem_bytes);
    dim3 grid(N_TILES / TILES_PER_CTA);  // 1024 CTAs
    ca_mma_kernel<<<grid, NTHR, smem_bytes>>>(x, w0, b0, w1, rand_u, out);
}

// round 17
// speedup vs baseline: 1.4482x; 1.2723x over previous
#include <cuda_runtime.h>
#include <cstdint>

#define HW   512
#define NTHR 256
#define TPW  34
#define TPH  6
#define XS_CH (TPH * TPW)        // 204
#define TILES_PER_CTA 8
#define N_TILES 8192             // 4 batches * 16 * 128 tiles of 32x4

// smem layout (float offsets)
// xs double-buffered. Region at REG_OFF time-shared: startup {w0 staging, b0} ->
// per tile: ys (features) -> H (after GEMM1, barrier-protected).
#define XS_SZ  3264              // [16][204]
#define XS_OFF 0                 // 2 buffers: 6528
#define REG_OFF 6528
#define YS_STR 136               // ys: [48][136] = 6528 (in region)
#define H_STR  136               // H:  [128][136] = 17408 (region size)
#define W0_OFF REG_OFF           // staging [128][48] = 6144 (startup only)
#define B0_OFF (REG_OFF + 6144)  // staging 128 (startup only)
#define W1_STR 132
#define W1_OFF (REG_OFF + 17408)        // 23936 ; [16][132] = 2112
#define SM_FLOATS (W1_OFF + 2112)       // 26048 floats = 104192 B

__device__ __forceinline__ float tf32f(float f) {
    uint32_t u;
    asm("cvt.rna.tf32.f32 %0, %1;" : "=r"(u) : "f"(f));
    return __uint_as_float(u);
}

// D += A(16x8) * B(8x8), tf32 inputs, f32 accumulate
__device__ __forceinline__ void mma8(float* d, const float* a, float b0, float b1) {
    asm("mma.sync.aligned.m16n8k8.row.col.f32.tf32.tf32.f32 "
        "{%0,%1,%2,%3}, {%4,%5,%6,%7}, {%8,%9}, {%0,%1,%2,%3};"
        : "+f"(d[0]), "+f"(d[1]), "+f"(d[2]), "+f"(d[3])
        : "r"(__float_as_uint(a[0])), "r"(__float_as_uint(a[1])),
          "r"(__float_as_uint(a[2])), "r"(__float_as_uint(a[3])),
          "r"(__float_as_uint(b0)), "r"(__float_as_uint(b1)));
}

__device__ __forceinline__ void cp4(uint32_t saddr, const float* g, int sz) {
    asm volatile("cp.async.ca.shared.global [%0], [%1], 4, %2;"
                 :: "r"(saddr), "l"(g), "r"(sz));
}

__global__ __launch_bounds__(NTHR, 2)
void ca_mma_kernel(const float* __restrict__ x,
                   const float* __restrict__ w0,
                   const float* __restrict__ b0,
                   const float* __restrict__ w1,
                   const float* __restrict__ rand_u,
                   float* __restrict__ out)
{
    extern __shared__ float sm[];
    float* ys  = sm + REG_OFF;
    float* Hs  = sm + REG_OFF;
    float* w0s = sm + W0_OFF;   // startup staging, aliased with region
    float* b0s = sm + B0_OFF;   // startup staging, aliased with region
    float* w1s = sm + W1_OFF;

    const int tid  = threadIdx.x;
    const int lane = tid & 31;
    const int wid  = tid >> 5;
    const int g    = lane >> 2;   // groupID
    const int t    = lane & 3;    // thread-in-group

    // halo loader role: threads 0..203 each handle one (hy,hx), 16 channels
    const int hpos = tid;
    const int hhy  = hpos / TPW;
    const int hhx  = hpos - hhy * TPW;

    const int tile0 = blockIdx.x * TILES_PER_CTA;

    // ---- prefetch tile0 halo into xs buf0 (before anything else) ----
    {
        const int tt = tile0;
        const int b = tt >> 11, rem = tt & 2047;
        const int gh0p = (rem >> 4) * 4, gw0p = (rem & 15) * 32;
        if (hpos < XS_CH) {
            const int gh = gh0p + hhy - 1, gw = gw0p + hhx - 1;
            const bool ok = (gh >= 0) && (gh < HW) && (gw >= 0) && (gw < HW);
            const float* gp = ok ? x + ((size_t)b << 22) + ((size_t)(gh << 9) + gw) : x;
            const int sz = ok ? 4 : 0;
            uint32_t sa = (uint32_t)__cvta_generic_to_shared(sm + XS_OFF + hpos);
            #pragma unroll
            for (int c = 0; c < 16; c++)
                cp4(sa + (uint32_t)(c * XS_CH) * 4u, gp + ((size_t)c << 18), sz);
        }
        asm volatile("cp.async.commit_group;" ::: "memory");
    }

    // ---- stage weights (tf32-rounded) ----
    for (int i = tid; i < 128 * 48; i += NTHR) w0s[i] = tf32f(w0[i]);
    for (int i = tid; i < 16 * 128; i += NTHR) {
        int r = i >> 7, c = i & 127;
        w1s[r * W1_STR + c] = tf32f(w1[i]);
    }
    if (tid < 128) b0s[tid] = b0[tid];
    __syncthreads();

    // ---- persistent W0 A-fragments: warp wid owns hid rows [16*wid, 16*wid+16) ----
    float a1f[6][4];
    {
        const int r0 = 16 * wid + g;
        #pragma unroll
        for (int s = 0; s < 6; s++) {
            a1f[s][0] = w0s[r0 * 48 + 8 * s + t];
            a1f[s][1] = w0s[(r0 + 8) * 48 + 8 * s + t];
            a1f[s][2] = w0s[r0 * 48 + 8 * s + t + 4];
            a1f[s][3] = w0s[(r0 + 8) * 48 + 8 * s + t + 4];
        }
    }
    const float bias0 = b0s[16 * wid + g];
    const float bias1 = b0s[16 * wid + g + 8];

    const int px_  = tid & 127;          // feature pixel for this thread
    const int fsel = tid >> 7;           // which 8 channels
    const int fpy  = px_ >> 5, fpx = px_ & 31;

    for (int it = 0; it < TILES_PER_CTA; ++it) {
        const int tile = tile0 + it;
        const int b    = tile >> 11;
        const int rem  = tile & 2047;
        const int gh0  = (rem >> 4) * 4;
        const int gw0  = (rem & 15) * 32;

        float* xsc = sm + XS_OFF + (it & 1) * XS_SZ;

        __syncthreads();   // guard: prev iter's xs/H readers done (also covers startup)

        // ---- issue prefetch for tile it+1 into the other xs buffer ----
        if (it + 1 < TILES_PER_CTA) {
            const int tt = tile + 1;
            const int bn = tt >> 11, remn = tt & 2047;
            const int gh0n = (remn >> 4) * 4, gw0n = (remn & 15) * 32;
            if (hpos < XS_CH) {
                const int gh = gh0n + hhy - 1, gw = gw0n + hhx - 1;
                const bool ok = (gh >= 0) && (gh < HW) && (gw >= 0) && (gw < HW);
                const float* gp = ok ? x + ((size_t)bn << 22) + ((size_t)(gh << 9) + gw) : x;
                const int sz = ok ? 4 : 0;
                uint32_t sa = (uint32_t)__cvta_generic_to_shared(
                                  sm + XS_OFF + ((it + 1) & 1) * XS_SZ + hpos);
                #pragma unroll
                for (int c = 0; c < 16; c++)
                    cp4(sa + (uint32_t)(c * XS_CH) * 4u, gp + ((size_t)c << 18), sz);
            }
            asm volatile("cp.async.commit_group;" ::: "memory");
            asm volatile("cp.async.wait_group 1;" ::: "memory");
        } else {
            asm volatile("cp.async.wait_group 0;" ::: "memory");
        }
        __syncthreads();   // publish xs[cur]

        // ---- features: this thread does 8 channels for pixel px_ ----
        {
            const int cb = fsel * 8;
            #pragma unroll
            for (int c = 0; c < 8; c++) {
                const float* p = xsc + (cb + c) * XS_CH + fpy * TPW + fpx;
                float a00 = p[0],       a01 = p[1],           a02 = p[2];
                float a10 = p[TPW],     a11 = p[TPW + 1],     a12 = p[TPW + 2];
                float a20 = p[2*TPW],   a21 = p[2*TPW + 1],   a22 = p[2*TPW + 2];
                float gx = (a02 - a00) + 2.f * (a12 - a10) + (a22 - a20);
                float gy = (a20 - a00) + 2.f * (a21 - a01) + (a22 - a02);
                ys[(cb + c) * YS_STR + px_]      = tf32f(a11);
                ys[(16 + cb + c) * YS_STR + px_] = tf32f(gx);
                ys[(32 + cb + c) * YS_STR + px_] = tf32f(gy);
            }
        }
        __syncthreads();

        // ---- GEMM1 for BOTH 64-px halves (exact R9 indices) ----
        float acc[2][8][4];
        #pragma unroll
        for (int sub = 0; sub < 2; sub++) {
            const int pxb = sub * 64;
            #pragma unroll
            for (int j = 0; j < 8; j++) {
                acc[sub][j][0] = bias0; acc[sub][j][1] = bias0;
                acc[sub][j][2] = bias1; acc[sub][j][3] = bias1;
            }
            #pragma unroll
            for (int s = 0; s < 6; s++) {
                const float* yb0 = ys + (8 * s + t) * YS_STR + pxb + g;
                const float* yb1 = ys + (8 * s + t + 4) * YS_STR + pxb + g;
                #pragma unroll
                for (int j = 0; j < 8; j++)
                    mma8(acc[sub][j], a1f[s], yb0[8 * j], yb1[8 * j]);
            }
        }
        __syncthreads();   // all ys reads done; region becomes H

        // ---- relu -> tf32 -> H[hid][128] (R9 addresses, float2-paired) ----
        {
            const int hr = 16 * wid + g;
            #pragma unroll
            for (int sub = 0; sub < 2; sub++) {
                #pragma unroll
                for (int j = 0; j < 8; j++) {
                    int cc = 64 * sub + 8 * j + 2 * t;
                    float2 v0 = { tf32f(fmaxf(acc[sub][j][0], 0.f)),
                                  tf32f(fmaxf(acc[sub][j][1], 0.f)) };
                    float2 v1 = { tf32f(fmaxf(acc[sub][j][2], 0.f)),
                                  tf32f(fmaxf(acc[sub][j][3], 0.f)) };
                    *(float2*)(Hs + hr * H_STR + cc)       = v0;
                    *(float2*)(Hs + (hr + 8) * H_STR + cc) = v1;
                }
            }
        }
        __syncthreads();   // H ready

        // ---- GEMM2: both halves in one k-loop (A fragments loaded once) ----
        float acc2[2][4] = {{0.f,0.f,0.f,0.f},{0.f,0.f,0.f,0.f}};
        #pragma unroll
        for (int s = 0; s < 16; s++) {
            float aa[4];
            aa[0] = w1s[g * W1_STR + 8 * s + t];
            aa[1] = w1s[(g + 8) * W1_STR + 8 * s + t];
            aa[2] = w1s[g * W1_STR + 8 * s + t + 4];
            aa[3] = w1s[(g + 8) * W1_STR + 8 * s + t + 4];
            const float* hb0 = Hs + (8 * s + t) * H_STR + 8 * wid + g;
            const float* hb1 = Hs + (8 * s + t + 4) * H_STR + 8 * wid + g;
            mma8(acc2[0], aa, hb0[0],  hb1[0]);
            mma8(acc2[1], aa, hb0[64], hb1[64]);
        }

        // ---- epilogue per half (R4 EXACT; mask read directly from rand_u) ----
        #pragma unroll
        for (int sub = 0; sub < 2; sub++) {
            const int cl = 8 * wid + 2 * t;      // chunk-local col (even)
            const int p  = 64 * sub + cl;        // pixel 0..126 (even)
            const int py = p >> 5, pxw = p & 31;
            const float2 ru = *(const float2*)(rand_u + (((size_t)b) << 18)
                                               + ((size_t)(gh0 + py) << 9) + gw0 + pxw);
            const float m0 = ru.x > 0.5f ? 1.f : 0.f;
            const float m1 = ru.y > 0.5f ? 1.f : 0.f;
            const int ch = g, ch2 = g + 8;
            const float* xc0 = xsc + ch  * XS_CH + (py + 1) * TPW + pxw + 1;
            const float* xc1 = xsc + ch2 * XS_CH + (py + 1) * TPW + pxw + 1;
            size_t o0 = ((size_t)(b * 16 + ch)  << 18) + ((size_t)(gh0 + py) << 9) + gw0 + pxw;
            size_t o1 = ((size_t)(b * 16 + ch2) << 18) + ((size_t)(gh0 + py) << 9) + gw0 + pxw;
            float2 v0 = { xc0[0] + acc2[sub][0] * m0, xc0[1] + acc2[sub][1] * m1 };
            float2 v1 = { xc1[0] + acc2[sub][2] * m0, xc1[1] + acc2[sub][3] * m1 };
            *(float2*)(out + o0) = v0;
            *(float2*)(out + o1) = v1;
        }
    }
}

extern "C" void kernel_launch(void* const* d_in, const int* in_sizes, int n_in,
                              void* d_out, int out_size)
{
    const float* x      = (const float*)d_in[0];
    const float* w0     = (const float*)d_in[1];
    const float* b0     = (const float*)d_in[2];
    const float* w1     = (const float*)d_in[3];
    const float* rand_u = (const float*)d_in[4];
    float* out = (float*)d_out;

    const int smem_bytes = SM_FLOATS * sizeof(float);   // 104192 B
    cudaFuncSetAttribute(ca_mma_kernel, cudaFuncAttributeMaxDynamicSharedMemorySize,
                         smem_bytes);
    dim3 grid(N_TILES / TILES_PER_CTA);  // 1024 CTAs
    ca_mma_kernel<<<grid, NTHR, smem_bytes>>>(x, w0, b0, w1, rand_u, out);
}